// round 3
// baseline (speedup 1.0000x reference)
#include <cuda_runtime.h>
#include <math.h>

// Elman RNN, fp32. B=128, S=1024, I=256, H=512, O=256, N_TARGETS=1.
// Phase A: P[t][b][j] = sum_i x[b,t,i]*W_i2h[j,i] + b_i2h[j]
// Phase B: persistent, 1024 steps. 128 CTAs = 8 j-tiles(64) x 16 b-tiles(8).
//          Wh tile resident in smem; full-K dot per CTA; tanh local;
//          double-buffered h; ONE 8-CTA group barrier per step.
// Phase C: output = h_T @ W_h2o^T + b_h2o ; hidden = h_T.

namespace {
constexpr int S = 1024, B = 128, I = 256, H = 512, O = 256;
constexpr int JT = 64;    // j per CTA
constexpr int BT = 8;     // b per CTA
constexpr int NJ = H / JT;   // 8 j-tiles
constexpr int NB = B / BT;   // 16 b-tiles (barrier groups)
constexpr int STR = 516;  // padded smem row stride (floats)
constexpr int SMEM_B_BYTES = (JT * STR + BT * STR) * 4;  // ~148.6 KB
}

__device__ float g_P[(size_t)S * B * H];   // [t][b][j] pre-activations (256 MB)
__device__ float g_Hbuf[2][B * H];         // ping-pong hidden state [b][k]
__device__ struct { unsigned v; unsigned pad[31]; } g_bar[NB];

__device__ __forceinline__ void group_barrier(unsigned* ctr, unsigned target) {
    __syncthreads();
    if (threadIdx.x == 0) {
        __threadfence();
        atomicAdd(ctr, 1u);
        unsigned v;
        do {
            asm volatile("ld.acquire.gpu.u32 %0, [%1];"
                         : "=r"(v) : "l"(ctr) : "memory");
        } while (v < target);
    }
    __syncthreads();
}

// ---------------- Phase A: pre-activation GEMM ----------------
// grid (S, H/128), 256 threads. CTA computes 128 j x 128 b for one t, K=I=256.
__global__ void __launch_bounds__(256) phaseA_kernel(
    const float* __restrict__ seq, const float* __restrict__ Wi2h,
    const float* __restrict__ bi2h) {
    const int t = blockIdx.x;
    const int j0 = blockIdx.y * 128;
    const int tid = threadIdx.x;
    const int tx = tid & 15;   // 8 b per thread
    const int ty = tid >> 4;   // 8 j per thread
    __shared__ float sh_a[128 * 16];  // [j][k]
    __shared__ float sh_b[16 * 128];  // [k][b]
    float acc[8][8];
#pragma unroll
    for (int r = 0; r < 8; r++)
#pragma unroll
        for (int c = 0; c < 8; c++) acc[r][c] = 0.f;

    for (int k0 = 0; k0 < I; k0 += 16) {
        __syncthreads();
#pragma unroll
        for (int q = 0; q < 2; q++) {
            int idx = tid + q * 256;  // 0..511
            int j = idx >> 2, kq = idx & 3;
            float4 v = *(const float4*)(Wi2h + (size_t)(j0 + j) * (I + H) + k0 + kq * 4);
            *(float4*)(sh_a + j * 16 + kq * 4) = v;
        }
#pragma unroll
        for (int q = 0; q < 2; q++) {
            int idx = tid + q * 256;
            int b = idx >> 2, kq = idx & 3;
            float4 v = *(const float4*)(seq + (size_t)b * (S * I) + (size_t)t * I + k0 + kq * 4);
            sh_b[(kq * 4 + 0) * 128 + b] = v.x;
            sh_b[(kq * 4 + 1) * 128 + b] = v.y;
            sh_b[(kq * 4 + 2) * 128 + b] = v.z;
            sh_b[(kq * 4 + 3) * 128 + b] = v.w;
        }
        __syncthreads();
#pragma unroll
        for (int k = 0; k < 16; k++) {
            float av[8];
#pragma unroll
            for (int r = 0; r < 8; r++) av[r] = sh_a[(ty * 8 + r) * 16 + k];
            float4 bv0 = *(const float4*)(sh_b + k * 128 + tx * 8);
            float4 bv1 = *(const float4*)(sh_b + k * 128 + tx * 8 + 4);
            float bv[8] = {bv0.x, bv0.y, bv0.z, bv0.w, bv1.x, bv1.y, bv1.z, bv1.w};
#pragma unroll
            for (int r = 0; r < 8; r++)
#pragma unroll
                for (int c = 0; c < 8; c++) acc[r][c] = fmaf(av[r], bv[c], acc[r][c]);
        }
    }
    // epilogue: write P as [t][b][j], add bias (bias indexed by j = row r)
    float bj[8];
#pragma unroll
    for (int r = 0; r < 8; r++) bj[r] = bi2h[j0 + ty * 8 + r];
#pragma unroll
    for (int c = 0; c < 8; c++) {
        int b = tx * 8 + c;
        float* op = g_P + (size_t)t * (B * H) + (size_t)b * H + j0 + ty * 8;
        float4 v0 = {acc[0][c] + bj[0], acc[1][c] + bj[1], acc[2][c] + bj[2], acc[3][c] + bj[3]};
        float4 v1 = {acc[4][c] + bj[4], acc[5][c] + bj[5], acc[6][c] + bj[6], acc[7][c] + bj[7]};
        *(float4*)op = v0;
        *(float4*)(op + 4) = v1;
    }
}

// ---------------- Phase B: persistent recurrence ----------------
__global__ void __launch_bounds__(256) phaseB_kernel(const float* __restrict__ Wi2h) {
    extern __shared__ float smem[];
    float* w_s = smem;             // [64j][516]  (k padded)
    float* h_s = smem + JT * STR;  // [8b][516]

    const int bb = blockIdx.x & 15;       // barrier group / b-tile
    const int jj = blockIdx.x >> 4;       // j-tile
    const int j0 = jj * JT;
    const int b0 = bb * BT;
    const int tid = threadIdx.x;
    const int jl = tid >> 2;              // 0..63 local j
    const int p = tid & 3;                // 0..3 -> local b pair {2p, 2p+1}

    // Load Wh tile once: w_s[j][k] = Wi2h[(j0+j)*(I+H) + I + k]
#pragma unroll
    for (int q = 0; q < 32; q++) {
        int idx = tid + q * 256;          // 0..8191 float4 slots
        int j = idx >> 7, kq = idx & 127;
        float4 v = *(const float4*)(Wi2h + (size_t)(j0 + j) * (I + H) + I + kq * 4);
        *(float4*)(w_s + j * STR + kq * 4) = v;
    }

    unsigned* ctr = &g_bar[bb].v;
    const float4* wp = (const float4*)(w_s + jl * STR);
    const float4* hp0 = (const float4*)(h_s + (2 * p) * STR);
    const float4* hp1 = (const float4*)(h_s + (2 * p + 1) * STR);

    for (int t = 0; t < S; t++) {
        const float* rbuf = g_Hbuf[t & 1];
        float* wbuf = g_Hbuf[(t + 1) & 1];
        // stage h slice: rows b0..b0+7, 512 floats each
        __syncthreads();  // protect h_s from previous step's readers
#pragma unroll
        for (int q = 0; q < 4; q++) {
            int idx = tid + q * 256;      // 0..1023 float4 slots
            int b = idx >> 7, kq = idx & 127;
            float4 v = *(const float4*)(rbuf + (size_t)(b0 + b) * H + kq * 4);
            *(float4*)(h_s + b * STR + kq * 4) = v;
        }
        __syncthreads();

        float4 c0 = {0.f, 0.f, 0.f, 0.f};
        float4 c1 = {0.f, 0.f, 0.f, 0.f};
#pragma unroll 8
        for (int q = 0; q < H / 4; q++) {
            float4 w = wp[q];
            float4 a = hp0[q];
            float4 b = hp1[q];
            c0.x = fmaf(w.x, a.x, c0.x);
            c0.y = fmaf(w.y, a.y, c0.y);
            c0.z = fmaf(w.z, a.z, c0.z);
            c0.w = fmaf(w.w, a.w, c0.w);
            c1.x = fmaf(w.x, b.x, c1.x);
            c1.y = fmaf(w.y, b.y, c1.y);
            c1.z = fmaf(w.z, b.z, c1.z);
            c1.w = fmaf(w.w, b.w, c1.w);
        }
        float acc0 = (c0.x + c0.y) + (c0.z + c0.w);
        float acc1 = (c1.x + c1.y) + (c1.z + c1.w);

        const float* pP = g_P + (size_t)t * (B * H);
        int gb0 = b0 + 2 * p, gb1 = gb0 + 1;
        float h0 = tanhf(acc0 + pP[(size_t)gb0 * H + j0 + jl]);
        float h1 = tanhf(acc1 + pP[(size_t)gb1 * H + j0 + jl]);
        wbuf[(size_t)gb0 * H + j0 + jl] = h0;
        wbuf[(size_t)gb1 * H + j0 + jl] = h1;

        group_barrier(ctr, (unsigned)(t + 1) * NJ);
    }
}

// ---------------- Phase C: output projection + hidden emit ----------------
__global__ void __launch_bounds__(256) phaseC_kernel(
    const float* __restrict__ Wh2o, const float* __restrict__ bh2o,
    float* __restrict__ out, int out_size) {
    const float* hfin = g_Hbuf[S & 1];  // buffer written at final step
    int idx = blockIdx.x * 256 + threadIdx.x;  // 0..32767
    int b = idx >> 8, o = idx & 255;
    float4 c = {0.f, 0.f, 0.f, 0.f};
    const float4* wrow = (const float4*)(Wh2o + (size_t)o * H);
    const float4* hrow = (const float4*)(hfin + (size_t)b * H);
#pragma unroll 8
    for (int q = 0; q < H / 4; q++) {
        float4 w = wrow[q];
        float4 h = hrow[q];
        c.x = fmaf(w.x, h.x, c.x);
        c.y = fmaf(w.y, h.y, c.y);
        c.z = fmaf(w.z, h.z, c.z);
        c.w = fmaf(w.w, h.w, c.w);
    }
    float acc = bh2o[o] + (c.x + c.y) + (c.z + c.w);
    if (idx < out_size) out[idx] = acc;  // output (B,1,O): idx = b*256+o
    // hidden (B,H) appended after the output if the harness expects it
    if (out_size >= B * O + B * H) {
#pragma unroll
        for (int q = 0; q < 2; q++) {
            int e = idx + q * (B * O);  // 0..65535
            int hb = e >> 9, hk = e & 511;
            out[B * O + e] = hfin[(size_t)hb * H + hk];
        }
    }
}

extern "C" void kernel_launch(void* const* d_in, const int* in_sizes, int n_in,
                              void* d_out, int out_size) {
    const float* seq  = (const float*)d_in[0];
    const float* Wi2h = (const float*)d_in[1];
    const float* bi2h = (const float*)d_in[2];
    const float* Wh2o = (const float*)d_in[3];
    const float* bh2o = (const float*)d_in[4];
    float* out = (float*)d_out;

    cudaFuncSetAttribute(phaseB_kernel,
                         cudaFuncAttributeMaxDynamicSharedMemorySize, SMEM_B_BYTES);

    void* pBar = nullptr;
    cudaGetSymbolAddress(&pBar, g_bar);
    cudaMemsetAsync(pBar, 0, sizeof(g_bar), 0);
    void* pH = nullptr;
    cudaGetSymbolAddress(&pH, g_Hbuf);
    cudaMemsetAsync(pH, 0, (size_t)B * H * sizeof(float), 0);  // buf[0] = h0 = 0

    phaseA_kernel<<<dim3(S, H / 128), 256>>>(seq, Wi2h, bi2h);
    phaseB_kernel<<<NJ * NB, 256, SMEM_B_BYTES>>>(Wi2h);
    phaseC_kernel<<<(B * O) / 256, 256>>>(Wh2o, bh2o, out, out_size);
}

// round 4
// speedup vs baseline: 1.7461x; 1.7461x over previous
#include <cuda_runtime.h>
#include <math.h>

// Elman RNN, fp32. B=128, S=1024, I=256, H=512, O=256, N_TARGETS=1.
// Phase A: P[t][j][b] = sum_i x[b,t,i]*W_i2h[j,i] + b_i2h[j]
// Phase B: persistent, 128 CTAs = 8 j-tiles(64) x 16 b-tiles(8).
//          warp = k-slice (8 x 64), thread tile 8j x 2b, packed f32x2 FMA,
//          smem partial reduction, double-buffered h[j][b],
//          one 8-arrival release/acquire barrier per step (no threadfence).
// Phase C: output = h_T @ W_h2o^T + b_h2o ; hidden appended if requested.

typedef unsigned long long ull;

namespace {
constexpr int S = 1024, B = 128, I = 256, H = 512, O = 256;
constexpr int NJ = 8, NB = 16;      // j-tiles, b-tiles (128 CTAs)
constexpr int JT = 64, BT = 8;      // CTA tile
constexpr int KZ = 8;               // k-slices (one per warp)
constexpr int KSL = H / KZ;         // 64
constexpr int PBS = 70;             // partial b-row stride (floats)
constexpr int PB = BT * PBS;        // 560 floats per kz plane
constexpr int W_S_FLOATS = H * JT;  // 32768 (128 KB)
constexpr int H_S_FLOATS = H * BT;  // 4096  (16 KB)
constexpr int P_S_FLOATS = KZ * PB; // 4480  (17.5 KB)
constexpr int SMEM_B_BYTES = (W_S_FLOATS + H_S_FLOATS + P_S_FLOATS) * 4;
}

__device__ float g_P[(size_t)S * H * B];   // [t][j][b] pre-activations (256 MB)
__device__ float g_Hbuf[2][H * B];         // ping-pong hidden state [j][b]
__device__ struct { unsigned v; unsigned pad[31]; } g_bar[NB];

__device__ __forceinline__ ull pack2(float x) {
    ull r;
    asm("mov.b64 %0, {%1, %1};" : "=l"(r) : "f"(x));
    return r;
}
__device__ __forceinline__ void fma2(ull& d, ull a, ull b) {
    asm("fma.rn.f32x2 %0, %1, %2, %0;" : "+l"(d) : "l"(a), "l"(b));
}

// ---------------- Phase A: pre-activation GEMM (unchanged from R2) ----------
__global__ void __launch_bounds__(256) phaseA_kernel(
    const float* __restrict__ seq, const float* __restrict__ Wi2h,
    const float* __restrict__ bi2h) {
    const int t = blockIdx.x;
    const int j0 = blockIdx.y * 128;
    const int tid = threadIdx.x;
    const int tx = tid & 15;   // 8 b per thread
    const int ty = tid >> 4;   // 8 j per thread
    __shared__ float sh_a[128 * 16];  // [j][k]
    __shared__ float sh_b[16 * 128];  // [k][b]
    float acc[8][8];
#pragma unroll
    for (int r = 0; r < 8; r++)
#pragma unroll
        for (int c = 0; c < 8; c++) acc[r][c] = 0.f;

    for (int k0 = 0; k0 < I; k0 += 16) {
        __syncthreads();
#pragma unroll
        for (int q = 0; q < 2; q++) {
            int idx = tid + q * 256;  // 0..511
            int j = idx >> 2, kq = idx & 3;
            float4 v = *(const float4*)(Wi2h + (size_t)(j0 + j) * (I + H) + k0 + kq * 4);
            *(float4*)(sh_a + j * 16 + kq * 4) = v;
        }
#pragma unroll
        for (int q = 0; q < 2; q++) {
            int idx = tid + q * 256;
            int b = idx >> 2, kq = idx & 3;
            float4 v = *(const float4*)(seq + (size_t)b * (S * I) + (size_t)t * I + k0 + kq * 4);
            sh_b[(kq * 4 + 0) * 128 + b] = v.x;
            sh_b[(kq * 4 + 1) * 128 + b] = v.y;
            sh_b[(kq * 4 + 2) * 128 + b] = v.z;
            sh_b[(kq * 4 + 3) * 128 + b] = v.w;
        }
        __syncthreads();
#pragma unroll
        for (int k = 0; k < 16; k++) {
            float av[8];
#pragma unroll
            for (int r = 0; r < 8; r++) av[r] = sh_a[(ty * 8 + r) * 16 + k];
            float4 bv0 = *(const float4*)(sh_b + k * 128 + tx * 8);
            float4 bv1 = *(const float4*)(sh_b + k * 128 + tx * 8 + 4);
            float bv[8] = {bv0.x, bv0.y, bv0.z, bv0.w, bv1.x, bv1.y, bv1.z, bv1.w};
#pragma unroll
            for (int r = 0; r < 8; r++)
#pragma unroll
                for (int c = 0; c < 8; c++) acc[r][c] = fmaf(av[r], bv[c], acc[r][c]);
        }
    }
#pragma unroll
    for (int r = 0; r < 8; r++) {
        int j = j0 + ty * 8 + r;
        float bj = bi2h[j];
        float* op = g_P + (size_t)t * (H * B) + (size_t)j * B + tx * 8;
        float4 v0 = {acc[r][0] + bj, acc[r][1] + bj, acc[r][2] + bj, acc[r][3] + bj};
        float4 v1 = {acc[r][4] + bj, acc[r][5] + bj, acc[r][6] + bj, acc[r][7] + bj};
        *(float4*)op = v0;
        *(float4*)(op + 4) = v1;
    }
}

// ---------------- Phase B: persistent recurrence ----------------
__global__ void __launch_bounds__(256) phaseB_kernel(const float* __restrict__ Wi2h) {
    extern __shared__ float smem[];
    float* w_s = smem;                       // [512 k][64 j]
    float* h_s = smem + W_S_FLOATS;          // [512 k][8 b]
    float* p_s = h_s + H_S_FLOATS;           // [8 kz][8 b (stride 70)][64 j]

    const int bb = blockIdx.x & 15;          // b-tile / barrier group
    const int jj = blockIdx.x >> 4;          // j-tile
    const int j0 = jj * JT;
    const int b0 = bb * BT;
    const int tid = threadIdx.x;
    const int kz = tid >> 5;                 // warp id = k-slice
    const int lane = tid & 31;
    const int ty = lane >> 2;                // 0..7  -> j = ty*8 .. +8
    const int tx = lane & 3;                 // 0..3  -> b = tx*2, tx*2+1

    // Load Wh transposed into w_s[k][j]:  Wh[k][j] = Wi2h[(j0+j)*(I+H)+I+k]
#pragma unroll
    for (int q = 0; q < 32; q++) {
        int idx = tid + q * 256;             // 0..8191 float4 slots
        int j = idx >> 7, k4 = idx & 127;
        float4 v = *(const float4*)(Wi2h + (size_t)(j0 + j) * (I + H) + I + k4 * 4);
        w_s[(k4 * 4 + 0) * JT + j] = v.x;
        w_s[(k4 * 4 + 1) * JT + j] = v.y;
        w_s[(k4 * 4 + 2) * JT + j] = v.z;
        w_s[(k4 * 4 + 3) * JT + j] = v.w;
    }

    unsigned* ctr = &g_bar[bb].v;
    const int jl1 = tid >> 3;                // reducer output 1: j local 0..31
    const int jl2 = 32 + jl1;                // reducer output 2: j local 32..63
    const int bl = tid & 7;

    const float* wp = w_s + kz * KSL * JT + ty * 8;
    const float* hp = h_s + kz * KSL * BT + tx * 2;

    for (int t = 0; t < S; t++) {
        const float* rbuf = g_Hbuf[t & 1];
        float* wbuf = g_Hbuf[(t + 1) & 1];

        // P prefetch (DRAM latency hidden under compute)
        const float* pP = g_P + (size_t)t * (H * B) + (size_t)j0 * B + b0;
        float p1 = pP[jl1 * B + bl];
        float p2 = pP[jl2 * B + bl];

        // stage h slice: h_s[k][b] <- rbuf[k][b0..b0+8)   (conflict-free STS.128)
#pragma unroll
        for (int q = 0; q < 4; q++) {
            int idx = tid + q * 256;         // 0..1023
            int k = idx >> 1, half = idx & 1;
            float4 v = *(const float4*)(rbuf + k * B + b0 + half * 4);
            *(float4*)(h_s + k * BT + half * 4) = v;
        }
        __syncthreads();

        // main k-slice loop: 8j x 2b per thread, packed f32x2 FMA
        ull acc00 = 0, acc01 = 0, acc10 = 0, acc11 = 0;
        ull acc20 = 0, acc21 = 0, acc30 = 0, acc31 = 0;
#pragma unroll 8
        for (int kk = 0; kk < KSL; kk++) {
            ulonglong2 wA = *(const ulonglong2*)(wp + kk * JT);
            ulonglong2 wB = *(const ulonglong2*)(wp + kk * JT + 4);
            float2 hv = *(const float2*)(hp + kk * BT);
            ull h0 = pack2(hv.x);
            ull h1 = pack2(hv.y);
            fma2(acc00, wA.x, h0); fma2(acc01, wA.x, h1);
            fma2(acc10, wA.y, h0); fma2(acc11, wA.y, h1);
            fma2(acc20, wB.x, h0); fma2(acc21, wB.x, h1);
            fma2(acc30, wB.y, h0); fma2(acc31, wB.y, h1);
        }

        // store partials: p_s[kz][b][j], u64 covers j pair (aligned, even offsets)
        {
            float* base = p_s + kz * PB + (tx * 2) * PBS + ty * 8;
            *(ull*)(base + 0) = acc00;  *(ull*)(base + PBS + 0) = acc01;
            *(ull*)(base + 2) = acc10;  *(ull*)(base + PBS + 2) = acc11;
            *(ull*)(base + 4) = acc20;  *(ull*)(base + PBS + 4) = acc21;
            *(ull*)(base + 6) = acc30;  *(ull*)(base + PBS + 6) = acc31;
        }
        __syncthreads();

        // reduce 8 k-slice partials + P, tanh, write h (sector-exact STG)
        {
            float s1 = p1, s2 = p2;
#pragma unroll
            for (int z = 0; z < KZ; z++) {
                s1 += p_s[z * PB + bl * PBS + jl1];
                s2 += p_s[z * PB + bl * PBS + jl2];
            }
            wbuf[(j0 + jl1) * B + b0 + bl] = tanhf(s1);
            wbuf[(j0 + jl2) * B + b0 + bl] = tanhf(s2);
        }

        // group barrier: release-add + acquire-spin (no threadfence / L1 flush)
        __syncthreads();
        if (tid == 0) {
            asm volatile("red.release.gpu.global.add.u32 [%0], 1;"
                         :: "l"(ctr) : "memory");
            unsigned v;
            unsigned target = (unsigned)(t + 1) * NJ;
            do {
                asm volatile("ld.acquire.gpu.u32 %0, [%1];"
                             : "=r"(v) : "l"(ctr) : "memory");
            } while (v < target);
        }
        __syncthreads();
    }
}

// ---------------- Phase C: output projection + hidden emit ----------------
__global__ void __launch_bounds__(256) phaseC_kernel(
    const float* __restrict__ Wh2o, const float* __restrict__ bh2o,
    float* __restrict__ out, int out_size) {
    const float* hfin = g_Hbuf[S & 1];       // buffer written at final step
    int idx = blockIdx.x * 256 + threadIdx.x;  // 0..32767
    int o = idx >> 7, b = idx & 127;         // lanes span b -> hfin coalesced
    float acc = bh2o[o];
#pragma unroll 8
    for (int k = 0; k < H; k++) {
        acc = fmaf(hfin[k * B + b], __ldg(Wh2o + (size_t)o * H + k), acc);
    }
    int oidx = b * O + o;                    // output (B,1,O)
    if (oidx < out_size) out[oidx] = acc;
    if (out_size >= B * O + B * H) {
#pragma unroll
        for (int q = 0; q < 2; q++) {
            int e = idx + q * (B * O);       // 0..65535
            int hb = e >> 9, hk = e & 511;
            out[B * O + e] = hfin[hk * B + hb];
        }
    }
}

extern "C" void kernel_launch(void* const* d_in, const int* in_sizes, int n_in,
                              void* d_out, int out_size) {
    const float* seq  = (const float*)d_in[0];
    const float* Wi2h = (const float*)d_in[1];
    const float* bi2h = (const float*)d_in[2];
    const float* Wh2o = (const float*)d_in[3];
    const float* bh2o = (const float*)d_in[4];
    float* out = (float*)d_out;

    cudaFuncSetAttribute(phaseB_kernel,
                         cudaFuncAttributeMaxDynamicSharedMemorySize, SMEM_B_BYTES);

    void* pBar = nullptr;
    cudaGetSymbolAddress(&pBar, g_bar);
    cudaMemsetAsync(pBar, 0, sizeof(g_bar), 0);
    void* pH = nullptr;
    cudaGetSymbolAddress(&pH, g_Hbuf);
    cudaMemsetAsync(pH, 0, (size_t)H * B * sizeof(float), 0);  // buf[0] = h0 = 0

    phaseA_kernel<<<dim3(S, H / 128), 256>>>(seq, Wi2h, bi2h);
    phaseB_kernel<<<NJ * NB, 256, SMEM_B_BYTES>>>(Wi2h);
    phaseC_kernel<<<(B * O) / 256, 256>>>(Wh2o, bh2o, out, out_size);
}